// round 9
// baseline (speedup 1.0000x reference)
#include <cuda_runtime.h>
#include <cuda_fp16.h>
#include <cstdint>

#define Hh 160
#define Ww 160
#define Bn 4
#define HW (Hh*Ww)

// ---------------- scratch (device globals; no allocation allowed) ----------------
// split-fp16 activations: [pix][chunk][hi 32 halfs | lo 32 halfs]  (64 halfs per chunk)
__device__ __align__(16) __half g_lrs[(size_t)Bn*HW*2*64];   // lr, 2 chunks (64ch)
__device__ __align__(16) __half g_hrs[(size_t)Bn*HW*2*64];   // hr, 2 chunks
__device__ __align__(16) __half g_h1s[(size_t)Bn*HW*4*64];   // conv1 out, 4 chunks (128ch)
__device__ __align__(16) __half g_h2s[(size_t)Bn*HW*4*64];   // conv2 out, 4 chunks
__device__ float g_hrT[(size_t)Bn*HW*64];                    // hr NHWC fp32 (deform gather)
__device__ float g_off[(size_t)Bn*HW*32];                    // offsets NHWC (18 used, pad 32)
// weights pre-split fp16 hi/lo, pre-swizzled smem image: [kc][oc][128 bytes]
__device__ __align__(16) __half g_BT1[36*128*64];
__device__ __align__(16) __half g_BT2[36*128*64];
__device__ __align__(16) __half g_BTo[36*32*64];
__device__ __align__(16) __half g_BTd[18*64*64];

// ---------------- helpers ----------------
__device__ __forceinline__ uint32_t smem_u32(const void* p) {
    uint32_t a;
    asm("{ .reg .u64 t; cvta.to.shared.u64 t, %1; cvt.u32.u64 %0, t; }" : "=r"(a) : "l"(p));
    return a;
}
__device__ __forceinline__ void ldm4(uint32_t* r, uint32_t addr) {
    asm volatile("ldmatrix.sync.aligned.m8n8.x4.shared.b16 {%0,%1,%2,%3}, [%4];"
                 : "=r"(r[0]), "=r"(r[1]), "=r"(r[2]), "=r"(r[3]) : "r"(addr));
}
__device__ __forceinline__ void mma16816(float* c, const uint32_t* a, const uint32_t* b) {
    asm volatile("mma.sync.aligned.m16n8k16.row.col.f32.f16.f16.f32 "
                 "{%0,%1,%2,%3}, {%4,%5,%6,%7}, {%8,%9}, {%0,%1,%2,%3};"
                 : "+f"(c[0]), "+f"(c[1]), "+f"(c[2]), "+f"(c[3])
                 : "r"(a[0]), "r"(a[1]), "r"(a[2]), "r"(a[3]), "r"(b[0]), "r"(b[1]));
}
__device__ __forceinline__ void st128(uint32_t a, uint4 v) {
    asm volatile("st.shared.v4.b32 [%0], {%1,%2,%3,%4};"
                 :: "r"(a), "r"(v.x), "r"(v.y), "r"(v.z), "r"(v.w) : "memory");
}
__device__ __forceinline__ void cp16(uint32_t dst, const void* src, int szbytes) {
    asm volatile("cp.async.cg.shared.global [%0], [%1], 16, %2;"
                 :: "r"(dst), "l"(src), "r"(szbytes) : "memory");
}
#define CP_COMMIT() asm volatile("cp.async.commit_group;" ::: "memory")
__device__ __forceinline__ uint32_t packh2(__half a, __half b) {
    __half2 h = __halves2half2(a, b);
    return *reinterpret_cast<uint32_t*>(&h);
}
__device__ __forceinline__ void split8(float4 u, float4 v, uint4& hi, uint4& lo) {
    float f[8] = {u.x,u.y,u.z,u.w, v.x,v.y,v.z,v.w};
    __half h[8], l[8];
    #pragma unroll
    for (int i = 0; i < 8; i++) {
        h[i] = __float2half_rn(f[i]);
        l[i] = __float2half_rn(f[i] - __half2float(h[i]));
    }
    hi = make_uint4(packh2(h[0],h[1]), packh2(h[2],h[3]), packh2(h[4],h[5]), packh2(h[6],h[7]));
    lo = make_uint4(packh2(l[0],l[1]), packh2(l[2],l[3]), packh2(l[4],l[5]), packh2(l[6],l[7]));
}

// ======= 3x3 conv implicit GEMM: 128 threads, 4 warps, warp tile 64 x (N/WN) =======
// cp.async staging, 3 stages, pre-split fp16 NHWC in. Term-major MMA emission
// (all ah*bh, then ah*bl, then al*bh) so same-accumulator RAW chains are 8 apart.
template<int N, int WN, int OUTK, bool RELU, int NCH, int CPT>
__global__ void __launch_bounds__(128, 2)
mma_conv_cp(const __half* __restrict__ in0h, const __half* __restrict__ in1h,
            const __half* __restrict__ BT, const float* __restrict__ bias,
            float* __restrict__ outf, __half* __restrict__ outh,
            int S0, int S1, int C0CH, int OUT_CS)
{
    constexpr int WM = 4 / WN;
    constexpr int MT = 128 / WM;
    constexpr int NT = N / WN;
    constexpr int MF = MT / 16;
    constexpr int NF = NT / 8;
    constexpr int ABUF = 128 * 128;
    constexpr int BBUF = N * 128;
    constexpr int STG  = 3;

    extern __shared__ __align__(16) char dsm[];
    const uint32_t smb = (smem_u32(dsm) + 127u) & ~127u;

    const int t = threadIdx.x;
    const int w = t >> 5, lane = t & 31;
    const int wm = w % WM, wn = w / WM;
    const int xb = blockIdx.x * 32, yb = blockIdx.y * 4, b = blockIdx.z;
    const int prow = t >> 5, pcol = t & 31;

    float acc[MF][NF][4];
    #pragma unroll
    for (int i = 0; i < MF; i++)
        #pragma unroll
        for (int j = 0; j < NF; j++)
            #pragma unroll
            for (int r = 0; r < 4; r++) acc[i][j][r] = 0.f;

    auto stage = [&](int kc) {
        const uint32_t base = smb + (uint32_t)(kc % STG) * (ABUF + BBUF);
        const int tap = kc / CPT, ckl = kc % CPT;
        const int gy = yb + prow + tap/3 - 1;
        const int gx = xb + pcol + tap%3 - 1;
        const bool ok = (gy >= 0 && gy < Hh && gx >= 0 && gx < Ww);
        const size_t pix = (size_t)b*HW + (size_t)(ok ? gy : 0)*Ww + (ok ? gx : 0);
        const __half* src = (ckl < C0CH)
            ? in0h + (pix*S0 + ckl) * 64
            : in1h + (pix*S1 + (ckl - C0CH)) * 64;
        const uint32_t arow = base + (uint32_t)t * 128;
        const int sw = t & 7;
        const int sz = ok ? 16 : 0;
        #pragma unroll
        for (int i = 0; i < 8; i++)
            cp16(arow + (uint32_t)((i ^ sw) << 4), src + i*8, sz);
        const __half* bsrc = BT + (size_t)kc*N*64;
        const uint32_t bb = base + ABUF;
        #pragma unroll
        for (int i = 0; i < N/16; i++)
            cp16(bb + (uint32_t)(t + i*128)*16, bsrc + (t + i*128)*8, 16);
        CP_COMMIT();
    };

    auto compute = [&](int kc) {
        const uint32_t Ab = smb + (uint32_t)(kc % STG) * (ABUF + BBUF);
        const uint32_t Bb = Ab + ABUF;
        #pragma unroll
        for (int ks = 0; ks < 2; ks++) {
            uint32_t ah[MF][4], al[MF][4];
            #pragma unroll
            for (int mf = 0; mf < MF; mf++) {
                const int row = wm*MT + mf*16 + (lane & 15);
                const int chh = ks*2 + (lane >> 4);
                const uint32_t rb = Ab + row*128;
                ldm4(ah[mf], rb + (uint32_t)((chh ^ (row&7)) << 4));
                ldm4(al[mf], rb + (uint32_t)(((chh+4) ^ (row&7)) << 4));
            }
            #pragma unroll
            for (int nf2 = 0; nf2 < NF/2; nf2++) {
                uint32_t bh[4], bl[4];
                const int oc  = wn*NT + nf2*16 + (lane & 7) + ((lane >> 4) << 3);
                const int chb = ks*2 + ((lane >> 3) & 1);
                const uint32_t rb = Bb + oc*128;
                ldm4(bh, rb + (uint32_t)((chb ^ (oc&7)) << 4));
                ldm4(bl, rb + (uint32_t)(((chb+4) ^ (oc&7)) << 4));
                // term-major: same-acc writes are 2*MF = 8 MMAs apart
                #pragma unroll
                for (int mf = 0; mf < MF; mf++) mma16816(acc[mf][2*nf2  ], ah[mf], bh+0);
                #pragma unroll
                for (int mf = 0; mf < MF; mf++) mma16816(acc[mf][2*nf2+1], ah[mf], bh+2);
                #pragma unroll
                for (int mf = 0; mf < MF; mf++) mma16816(acc[mf][2*nf2  ], ah[mf], bl+0);
                #pragma unroll
                for (int mf = 0; mf < MF; mf++) mma16816(acc[mf][2*nf2+1], ah[mf], bl+2);
                #pragma unroll
                for (int mf = 0; mf < MF; mf++) mma16816(acc[mf][2*nf2  ], al[mf], bh+0);
                #pragma unroll
                for (int mf = 0; mf < MF; mf++) mma16816(acc[mf][2*nf2+1], al[mf], bh+2);
            }
        }
    };

    stage(0);
    stage(1);
    for (int kc = 0; kc < NCH; kc++) {
        if (kc + 1 < NCH) { asm volatile("cp.async.wait_group 1;" ::: "memory"); }
        else              { asm volatile("cp.async.wait_group 0;" ::: "memory"); }
        __syncthreads();
        compute(kc);
        if (kc + STG - 1 < NCH) stage(kc + STG - 1);
    }

    // ---- epilogue ----
    const int lrow = lane >> 2, lcol = (lane & 3) * 2;
    #pragma unroll
    for (int mf = 0; mf < MF; mf++) {
        #pragma unroll
        for (int nf = 0; nf < NF; nf++) {
            const int oc = wn*NT + nf*8 + lcol;
            float bx = 0.f, by = 0.f;
            if (bias != nullptr) { bx = __ldg(bias + oc); by = __ldg(bias + oc + 1); }
            #pragma unroll
            for (int rp = 0; rp < 2; rp++) {
                const int m = wm*MT + mf*16 + lrow + rp*8;
                const int y = yb + (m >> 5), x = xb + (m & 31);
                float c0 = acc[mf][nf][rp*2] + bx;
                float c1 = acc[mf][nf][rp*2+1] + by;
                if (RELU) { c0 = fmaxf(c0, 0.f); c1 = fmaxf(c1, 0.f); }
                const size_t pix = (size_t)b*HW + (size_t)y*Ww + x;
                if (OUTK == 0) {
                    *(float2*)(outf + pix*OUT_CS + oc) = make_float2(c0, c1);
                } else {
                    __half h0 = __float2half_rn(c0);
                    __half l0 = __float2half_rn(c0 - __half2float(h0));
                    __half h1 = __float2half_rn(c1);
                    __half l1 = __float2half_rn(c1 - __half2float(h1));
                    __half* dst = outh + (pix*(N/32) + (oc >> 5))*64 + (oc & 31);
                    *(__half2*)dst        = __halves2half2(h0, h1);
                    *(__half2*)(dst + 32) = __halves2half2(l0, l1);
                }
            }
        }
    }
}

// ======= fused deformable sampling + 1x1 contraction (K=576 -> 64), fp32 NCHW out =======
__global__ void __launch_bounds__(256)
deform_mma(const float* __restrict__ in0f, const float* __restrict__ offp,
           const __half* __restrict__ BT, float* __restrict__ outf)
{
    constexpr int N = 64, NCH = 18;
    constexpr int MF = 2, NF = 4;          // WM=4 (MT=32), WN=2 (NT=32)
    constexpr int ABUF = 128 * 128;
    constexpr int BBUF = N * 128;
    constexpr int BV = N / 32;

    extern __shared__ __align__(16) char dsm[];
    const uint32_t smb = (smem_u32(dsm) + 127u) & ~127u;
    const uint32_t Ab0 = smb, Ab1 = smb + ABUF;
    const uint32_t Bb0 = smb + 2*ABUF, Bb1 = smb + 2*ABUF + BBUF;

    const int t = threadIdx.x;
    const int w = t >> 5, lane = t & 31;
    const int wm = w % 4, wn = w / 4;
    const int xb = blockIdx.x * 32, yb = blockIdx.y * 4, b = blockIdx.z;

    float acc[MF][NF][4];
    #pragma unroll
    for (int i = 0; i < MF; i++)
        #pragma unroll
        for (int j = 0; j < NF; j++)
            #pragma unroll
            for (int r = 0; r < 4; r++) acc[i][j][r] = 0.f;

    const int px = t >> 1, half = t & 1;
    const int prow = px >> 5, pcol = px & 31;

    float4 avf[4];
    uint4  bv[BV];
    const float *cp00 = nullptr, *cp01 = nullptr, *cp10 = nullptr, *cp11 = nullptr;
    float cw00 = 0.f, cw01 = 0.f, cw10 = 0.f, cw11 = 0.f;

    auto load_a = [&](int kc) {
        const int tap = kc >> 1;
        if ((kc & 1) == 0) {
            const int y = yb + prow, x = xb + pcol;
            const size_t pix = (size_t)b*HW + (size_t)y*Ww + x;
            const float dy = offp[pix*32 + 2*tap];
            const float dx = offp[pix*32 + 2*tap + 1];
            const float py  = (float)(y + tap/3 - 1) + dy;
            const float pxx = (float)(x + tap%3 - 1) + dx;
            const float y0f = floorf(py), x0f = floorf(pxx);
            const float wy = py - y0f, wx = pxx - x0f;
            const int yi = (int)y0f, xi = (int)x0f;
            const bool vy0 = (yi   >= 0) && (yi   <= Hh-1);
            const bool vy1 = (yi+1 >= 0) && (yi+1 <= Hh-1);
            const bool vx0 = (xi   >= 0) && (xi   <= Ww-1);
            const bool vx1 = (xi+1 >= 0) && (xi+1 <= Ww-1);
            const int yc0 = min(max(yi,   0), Hh-1);
            const int yc1 = min(max(yi+1, 0), Hh-1);
            const int xc0 = min(max(xi,   0), Ww-1);
            const int xc1 = min(max(xi+1, 0), Ww-1);
            cw00 = (1.f-wy)*(1.f-wx) * ((vy0 && vx0) ? 1.f : 0.f);
            cw01 = (1.f-wy)*wx       * ((vy0 && vx1) ? 1.f : 0.f);
            cw10 = wy*(1.f-wx)       * ((vy1 && vx0) ? 1.f : 0.f);
            cw11 = wy*wx             * ((vy1 && vx1) ? 1.f : 0.f);
            const float* base = in0f + (size_t)b*HW*64;
            cp00 = base + ((size_t)yc0*Ww + xc0)*64;
            cp01 = base + ((size_t)yc0*Ww + xc1)*64;
            cp10 = base + ((size_t)yc1*Ww + xc0)*64;
            cp11 = base + ((size_t)yc1*Ww + xc1)*64;
        }
        const int cb = ((kc & 1) << 5) + half * 16;
        const float4* p00 = (const float4*)(cp00 + cb);
        const float4* p01 = (const float4*)(cp01 + cb);
        const float4* p10 = (const float4*)(cp10 + cb);
        const float4* p11 = (const float4*)(cp11 + cb);
        #pragma unroll
        for (int i = 0; i < 4; i++) {
            float4 a = p00[i], bq = p01[i], c4 = p10[i], d = p11[i];
            avf[i].x = cw00*a.x + cw01*bq.x + cw10*c4.x + cw11*d.x;
            avf[i].y = cw00*a.y + cw01*bq.y + cw10*c4.y + cw11*d.y;
            avf[i].z = cw00*a.z + cw01*bq.z + cw10*c4.z + cw11*d.z;
            avf[i].w = cw00*a.w + cw01*bq.w + cw10*c4.w + cw11*d.w;
        }
    };
    auto load_b = [&](int kc) {
        const uint4* src = (const uint4*)(BT + (size_t)kc*N*64);
        #pragma unroll
        for (int i = 0; i < BV; i++) bv[i] = src[t + i*256];
    };
    auto sts_ab = [&](uint32_t Ab, uint32_t Bb) {
        const uint32_t rowb = Ab + px*128;
        const uint32_t sw = px & 7;
        #pragma unroll
        for (int i = 0; i < 2; i++) {
            uint4 hi, lo;
            split8(avf[2*i], avf[2*i+1], hi, lo);
            const int ch = half*2 + i;
            st128(rowb + (uint32_t)((ch ^ sw) << 4), hi);
            st128(rowb + (uint32_t)(((ch+4) ^ sw) << 4), lo);
        }
        #pragma unroll
        for (int i = 0; i < BV; i++) st128(Bb + (t + i*256)*16, bv[i]);
    };
    auto compute = [&](uint32_t Ab, uint32_t Bb) {
        #pragma unroll
        for (int ks = 0; ks < 2; ks++) {
            uint32_t ah[MF][4], al[MF][4];
            #pragma unroll
            for (int mf = 0; mf < MF; mf++) {
                const int row = wm*32 + mf*16 + (lane & 15);
                const int chh = ks*2 + (lane >> 4);
                const uint32_t rb = Ab + row*128;
                ldm4(ah[mf], rb + (uint32_t)((chh ^ (row&7)) << 4));
                ldm4(al[mf], rb + (uint32_t)(((chh+4) ^ (row&7)) << 4));
            }
            #pragma unroll
            for (int nf2 = 0; nf2 < NF/2; nf2++) {
                uint32_t bh[4], bl[4];
                const int oc  = wn*32 + nf2*16 + (lane & 7) + ((lane >> 4) << 3);
                const int chb = ks*2 + ((lane >> 3) & 1);
                const uint32_t rb = Bb + oc*128;
                ldm4(bh, rb + (uint32_t)((chb ^ (oc&7)) << 4));
                ldm4(bl, rb + (uint32_t)(((chb+4) ^ (oc&7)) << 4));
                // term-major ordering (same-acc writes 2*MF = 4 apart here)
                #pragma unroll
                for (int mf = 0; mf < MF; mf++) mma16816(acc[mf][2*nf2  ], ah[mf], bh+0);
                #pragma unroll
                for (int mf = 0; mf < MF; mf++) mma16816(acc[mf][2*nf2+1], ah[mf], bh+2);
                #pragma unroll
                for (int mf = 0; mf < MF; mf++) mma16816(acc[mf][2*nf2  ], ah[mf], bl+0);
                #pragma unroll
                for (int mf = 0; mf < MF; mf++) mma16816(acc[mf][2*nf2+1], ah[mf], bl+2);
                #pragma unroll
                for (int mf = 0; mf < MF; mf++) mma16816(acc[mf][2*nf2  ], al[mf], bh+0);
                #pragma unroll
                for (int mf = 0; mf < MF; mf++) mma16816(acc[mf][2*nf2+1], al[mf], bh+2);
            }
        }
    };

    load_a(0); load_b(0);
    sts_ab(Ab0, Bb0);
    __syncthreads();

    for (int kc = 0; kc < NCH; kc++) {
        if (kc + 1 < NCH) { load_a(kc+1); load_b(kc+1); }
        compute((kc & 1) ? Ab1 : Ab0, (kc & 1) ? Bb1 : Bb0);
        if (kc + 1 < NCH) {
            sts_ab(((kc+1) & 1) ? Ab1 : Ab0, ((kc+1) & 1) ? Bb1 : Bb0);
            __syncthreads();
        }
    }

    const int lrow = lane >> 2, lcol = (lane & 3) * 2;
    #pragma unroll
    for (int mf = 0; mf < MF; mf++) {
        #pragma unroll
        for (int nf = 0; nf < NF; nf++) {
            const int oc = wn*32 + nf*8 + lcol;
            #pragma unroll
            for (int rp = 0; rp < 2; rp++) {
                const int m = wm*32 + mf*16 + lrow + rp*8;
                const int y = yb + (m >> 5), x = xb + (m & 31);
                const size_t p = (size_t)y*Ww + x;
                outf[((size_t)b*N + oc  )*HW + p] = acc[mf][nf][rp*2];
                outf[((size_t)b*N + oc+1)*HW + p] = acc[mf][nf][rp*2+1];
            }
        }
    }
}

// ---------------- NCHW fp32 -> split fp16 NHWC chunks (+ optional fp32 NHWC copy) ----------------
__global__ void to_nhwc_split(const float* __restrict__ src, __half* __restrict__ dsts,
                              float* __restrict__ dstf, int C)
{
    __shared__ float tl[32][33];
    const int p0 = blockIdx.x*32, c0 = blockIdx.y*32, b = blockIdx.z;
    const int lx = threadIdx.x & 31, ly = threadIdx.x >> 5;
    #pragma unroll
    for (int i = 0; i < 32; i += 8)
        tl[ly+i][lx] = src[((size_t)b*C + c0 + ly + i)*HW + p0 + lx];
    __syncthreads();
    const int CPT = C / 32;
    #pragma unroll
    for (int i = 0; i < 32; i += 8) {
        const int pix = p0 + ly + i, c = c0 + lx;
        const float v = tl[lx][ly+i];
        __half h = __float2half_rn(v);
        __half l = __float2half_rn(v - __half2float(h));
        __half* d = dsts + (((size_t)b*HW + pix)*CPT + (c >> 5))*64 + (c & 31);
        d[0]  = h;
        d[32] = l;
        if (dstf != nullptr) dstf[((size_t)b*HW + pix)*C + c] = v;
    }
}

// ---------------- weight reformat: split fp16 hi/lo + pre-swizzle smem image ----------------
__global__ void reformat_w_split(const float* __restrict__ w, __half* __restrict__ BT,
                                 int COUT, int NPAD, int CIN, int TOT)
{
    int i = blockIdx.x*blockDim.x + threadIdx.x;
    if (i >= TOT) return;
    int j  = i & 31;
    int oc = (i >> 5) % NPAD;
    int kc = i / (32 * NPAD);
    int kidx = kc*32 + j;
    int tap = kidx / CIN, cin = kidx % CIN;
    float v = (oc < COUT) ? w[((size_t)oc*CIN + cin)*9 + tap] : 0.f;
    __half h = __float2half_rn(v);
    __half l = __float2half_rn(v - __half2float(h));
    int sw = oc & 7;
    size_t rowb = ((size_t)kc*NPAD + oc) * 64;
    int ch = j >> 3, pos = j & 7;
    BT[rowb + (size_t)(((ch    ) ^ sw) << 3) + pos] = h;
    BT[rowb + (size_t)(((ch + 4) ^ sw) << 3) + pos] = l;
}

// ---------------- launch ----------------
extern "C" void kernel_launch(void* const* d_in, const int* in_sizes, int n_in,
                              void* d_out, int out_size)
{
    (void)in_sizes; (void)n_in; (void)out_size;
    const float* lr = (const float*)d_in[0];
    const float* hr = (const float*)d_in[1];
    const float* w1 = (const float*)d_in[2];
    const float* b1 = (const float*)d_in[3];
    const float* w2 = (const float*)d_in[4];
    const float* b2 = (const float*)d_in[5];
    const float* wo = (const float*)d_in[6];
    const float* wd = (const float*)d_in[7];
    float* out = (float*)d_out;

    __half *plrs, *phrs, *ph1s, *ph2s, *pBT1, *pBT2, *pBTo, *pBTd;
    float *phrT, *poff;
    cudaGetSymbolAddress((void**)&plrs, g_lrs);
    cudaGetSymbolAddress((void**)&phrs, g_hrs);
    cudaGetSymbolAddress((void**)&ph1s, g_h1s);
    cudaGetSymbolAddress((void**)&ph2s, g_h2s);
    cudaGetSymbolAddress((void**)&phrT, g_hrT);
    cudaGetSymbolAddress((void**)&poff, g_off);
    cudaGetSymbolAddress((void**)&pBT1, g_BT1);
    cudaGetSymbolAddress((void**)&pBT2, g_BT2);
    cudaGetSymbolAddress((void**)&pBTo, g_BTo);
    cudaGetSymbolAddress((void**)&pBTd, g_BTd);

    const int SZ128 = 3*(16384 + 128*128);   // 98304
    const int SZ32  = 3*(16384 + 32*128);    // 61440
    const int SZD   = 2*16384 + 2*64*128;    // 49152
    cudaFuncSetAttribute(mma_conv_cp<128,2,1,true ,36,4>,
                         cudaFuncAttributeMaxDynamicSharedMemorySize, SZ128);
    cudaFuncSetAttribute(mma_conv_cp<32 ,1,0,false,36,4>,
                         cudaFuncAttributeMaxDynamicSharedMemorySize, SZ32);
    cudaFuncSetAttribute(deform_mma,
                         cudaFuncAttributeMaxDynamicSharedMemorySize, SZD);

    // launch order: conv1 at index 3 (ncu profiles launch index 3)
    reformat_w_split<<<(36*128*32+255)/256, 256>>>(w1, pBT1, 128, 128, 128, 36*128*32); // 0
    to_nhwc_split<<<dim3(800,2,Bn), 256>>>(lr, plrs, nullptr, 64);                      // 1
    to_nhwc_split<<<dim3(800,2,Bn), 256>>>(hr, phrs, phrT,    64);                      // 2

    // conv1: concat(lr|hr)(128) -> 128, relu, split-fp16 out   [launch 3: PROFILED]
    mma_conv_cp<128,2,1,true ,36,4><<<dim3(5,40,Bn), 128, SZ128>>>(
        plrs, phrs, pBT1, b1, nullptr, ph1s, 2, 2, 2, 0);

    reformat_w_split<<<(36*128*32+255)/256, 256>>>(w2, pBT2, 128, 128, 128, 36*128*32); // 4
    reformat_w_split<<<(36*32*32 +255)/256, 256>>>(wo, pBTo, 18,  32,  128, 36*32*32);  // 5
    reformat_w_split<<<(18*64*32 +255)/256, 256>>>(wd, pBTd, 64,  64,  64,  18*64*32);  // 6

    // conv2: 128 -> 128, relu, split-fp16 out
    mma_conv_cp<128,2,1,true ,36,4><<<dim3(5,40,Bn), 128, SZ128>>>(
        ph1s, ph1s, pBT2, b2, nullptr, ph2s, 4, 4, 4, 0);
    // offset conv: 128 -> 18 (pad 32), fp32 NHWC out
    mma_conv_cp<32 ,1,0,false,36,4><<<dim3(5,40,Bn), 128, SZ32 >>>(
        ph2s, ph2s, pBTo, nullptr, poff, nullptr, 4, 4, 4, 32);
    // fused deformable sampling + contraction: K=576 -> 64, fp32 NCHW out
    deform_mma<<<dim3(5,40,Bn), 256, SZD>>>(phrT, poff, pBTd, out);
}

// round 11
// speedup vs baseline: 1.0593x; 1.0593x over previous
#include <cuda_runtime.h>
#include <cuda_fp16.h>
#include <cstdint>

#define Hh 160
#define Ww 160
#define Bn 4
#define HW (Hh*Ww)

// ---------------- scratch (device globals; no allocation allowed) ----------------
// split-fp16 activations: [pix][chunk][hi 32 halfs | lo 32 halfs]  (64 halfs per chunk)
__device__ __align__(16) __half g_lrs[(size_t)Bn*HW*2*64];   // lr, 2 chunks (64ch)
__device__ __align__(16) __half g_hrs[(size_t)Bn*HW*2*64];   // hr, 2 chunks
__device__ __align__(16) __half g_h1s[(size_t)Bn*HW*4*64];   // conv1 out, 4 chunks (128ch)
__device__ __align__(16) __half g_h2s[(size_t)Bn*HW*4*64];   // conv2 out, 4 chunks
__device__ __align__(16) __half g_hrh[(size_t)Bn*HW*64];     // hr NHWC plain fp16 (deform gather)
__device__ float g_off[(size_t)Bn*HW*32];                    // offsets NHWC (18 used, pad 32)
// weights pre-split fp16 hi/lo, pre-swizzled smem image: [kc][oc][128 bytes]
__device__ __align__(16) __half g_BT1[36*128*64];
__device__ __align__(16) __half g_BT2[36*128*64];
__device__ __align__(16) __half g_BTo[36*32*64];
__device__ __align__(16) __half g_BTd[18*64*64];

// ---------------- helpers ----------------
__device__ __forceinline__ uint32_t smem_u32(const void* p) {
    uint32_t a;
    asm("{ .reg .u64 t; cvta.to.shared.u64 t, %1; cvt.u32.u64 %0, t; }" : "=r"(a) : "l"(p));
    return a;
}
__device__ __forceinline__ void ldm4(uint32_t* r, uint32_t addr) {
    asm volatile("ldmatrix.sync.aligned.m8n8.x4.shared.b16 {%0,%1,%2,%3}, [%4];"
                 : "=r"(r[0]), "=r"(r[1]), "=r"(r[2]), "=r"(r[3]) : "r"(addr));
}
__device__ __forceinline__ void mma16816(float* c, const uint32_t* a, const uint32_t* b) {
    asm volatile("mma.sync.aligned.m16n8k16.row.col.f32.f16.f16.f32 "
                 "{%0,%1,%2,%3}, {%4,%5,%6,%7}, {%8,%9}, {%0,%1,%2,%3};"
                 : "+f"(c[0]), "+f"(c[1]), "+f"(c[2]), "+f"(c[3])
                 : "r"(a[0]), "r"(a[1]), "r"(a[2]), "r"(a[3]), "r"(b[0]), "r"(b[1]));
}
__device__ __forceinline__ void st128(uint32_t a, uint4 v) {
    asm volatile("st.shared.v4.b32 [%0], {%1,%2,%3,%4};"
                 :: "r"(a), "r"(v.x), "r"(v.y), "r"(v.z), "r"(v.w) : "memory");
}
__device__ __forceinline__ void cp16(uint32_t dst, const void* src, int szbytes) {
    asm volatile("cp.async.cg.shared.global [%0], [%1], 16, %2;"
                 :: "r"(dst), "l"(src), "r"(szbytes) : "memory");
}
#define CP_COMMIT() asm volatile("cp.async.commit_group;" ::: "memory")
__device__ __forceinline__ uint32_t packh2(__half a, __half b) {
    __half2 h = __halves2half2(a, b);
    return *reinterpret_cast<uint32_t*>(&h);
}
__device__ __forceinline__ void split8(float4 u, float4 v, uint4& hi, uint4& lo) {
    float f[8] = {u.x,u.y,u.z,u.w, v.x,v.y,v.z,v.w};
    __half h[8], l[8];
    #pragma unroll
    for (int i = 0; i < 8; i++) {
        h[i] = __float2half_rn(f[i]);
        l[i] = __float2half_rn(f[i] - __half2float(h[i]));
    }
    hi = make_uint4(packh2(h[0],h[1]), packh2(h[2],h[3]), packh2(h[4],h[5]), packh2(h[6],h[7]));
    lo = make_uint4(packh2(l[0],l[1]), packh2(l[2],l[3]), packh2(l[4],l[5]), packh2(l[6],l[7]));
}
// load 16 contiguous fp16 channels -> 8 float2
__device__ __forceinline__ void gath16(const __half* p, float2* f) {
    uint4 q0 = *(const uint4*)p;
    uint4 q1 = *(const uint4*)(p + 8);
    uint32_t u[8] = {q0.x,q0.y,q0.z,q0.w, q1.x,q1.y,q1.z,q1.w};
    #pragma unroll
    for (int i = 0; i < 8; i++) f[i] = __half22float2(*(const __half2*)&u[i]);
}

// ======= 3x3 conv implicit GEMM: 128 threads, 4 warps, warp tile 64 x (N/WN) =======
// cp.async staging, 3 stages, pre-split fp16 NHWC in, 3-term split (ah*bh + ah*bl + al*bh).
template<int N, int WN, int OUTK, bool RELU, int NCH, int CPT>
__global__ void __launch_bounds__(128, 2)
mma_conv_cp(const __half* __restrict__ in0h, const __half* __restrict__ in1h,
            const __half* __restrict__ BT, const float* __restrict__ bias,
            float* __restrict__ outf, __half* __restrict__ outh,
            int S0, int S1, int C0CH, int OUT_CS)
{
    constexpr int WM = 4 / WN;
    constexpr int MT = 128 / WM;
    constexpr int NT = N / WN;
    constexpr int MF = MT / 16;
    constexpr int NF = NT / 8;
    constexpr int ABUF = 128 * 128;
    constexpr int BBUF = N * 128;
    constexpr int STG  = 3;

    extern __shared__ __align__(16) char dsm[];
    const uint32_t smb = (smem_u32(dsm) + 127u) & ~127u;

    const int t = threadIdx.x;
    const int w = t >> 5, lane = t & 31;
    const int wm = w % WM, wn = w / WM;
    const int xb = blockIdx.x * 32, yb = blockIdx.y * 4, b = blockIdx.z;
    const int prow = t >> 5, pcol = t & 31;

    float acc[MF][NF][4];
    #pragma unroll
    for (int i = 0; i < MF; i++)
        #pragma unroll
        for (int j = 0; j < NF; j++)
            #pragma unroll
            for (int r = 0; r < 4; r++) acc[i][j][r] = 0.f;

    auto stage = [&](int kc) {
        const uint32_t base = smb + (uint32_t)(kc % STG) * (ABUF + BBUF);
        const int tap = kc / CPT, ckl = kc % CPT;
        const int gy = yb + prow + tap/3 - 1;
        const int gx = xb + pcol + tap%3 - 1;
        const bool ok = (gy >= 0 && gy < Hh && gx >= 0 && gx < Ww);
        const size_t pix = (size_t)b*HW + (size_t)(ok ? gy : 0)*Ww + (ok ? gx : 0);
        const __half* src = (ckl < C0CH)
            ? in0h + (pix*S0 + ckl) * 64
            : in1h + (pix*S1 + (ckl - C0CH)) * 64;
        const uint32_t arow = base + (uint32_t)t * 128;
        const int sw = t & 7;
        const int sz = ok ? 16 : 0;
        #pragma unroll
        for (int i = 0; i < 8; i++)
            cp16(arow + (uint32_t)((i ^ sw) << 4), src + i*8, sz);
        const __half* bsrc = BT + (size_t)kc*N*64;
        const uint32_t bb = base + ABUF;
        #pragma unroll
        for (int i = 0; i < N/16; i++)
            cp16(bb + (uint32_t)(t + i*128)*16, bsrc + (t + i*128)*8, 16);
        CP_COMMIT();
    };

    auto compute = [&](int kc) {
        const uint32_t Ab = smb + (uint32_t)(kc % STG) * (ABUF + BBUF);
        const uint32_t Bb = Ab + ABUF;
        #pragma unroll
        for (int ks = 0; ks < 2; ks++) {
            uint32_t ah[MF][4], al[MF][4];
            #pragma unroll
            for (int mf = 0; mf < MF; mf++) {
                const int row = wm*MT + mf*16 + (lane & 15);
                const int chh = ks*2 + (lane >> 4);
                const uint32_t rb = Ab + row*128;
                ldm4(ah[mf], rb + (uint32_t)((chh ^ (row&7)) << 4));
                ldm4(al[mf], rb + (uint32_t)(((chh+4) ^ (row&7)) << 4));
            }
            #pragma unroll
            for (int nf2 = 0; nf2 < NF/2; nf2++) {
                uint32_t bh[4], bl[4];
                const int oc  = wn*NT + nf2*16 + (lane & 7) + ((lane >> 4) << 3);
                const int chb = ks*2 + ((lane >> 3) & 1);
                const uint32_t rb = Bb + oc*128;
                ldm4(bh, rb + (uint32_t)((chb ^ (oc&7)) << 4));
                ldm4(bl, rb + (uint32_t)(((chb+4) ^ (oc&7)) << 4));
                #pragma unroll
                for (int mf = 0; mf < MF; mf++) mma16816(acc[mf][2*nf2  ], ah[mf], bh+0);
                #pragma unroll
                for (int mf = 0; mf < MF; mf++) mma16816(acc[mf][2*nf2+1], ah[mf], bh+2);
                #pragma unroll
                for (int mf = 0; mf < MF; mf++) mma16816(acc[mf][2*nf2  ], ah[mf], bl+0);
                #pragma unroll
                for (int mf = 0; mf < MF; mf++) mma16816(acc[mf][2*nf2+1], ah[mf], bl+2);
                #pragma unroll
                for (int mf = 0; mf < MF; mf++) mma16816(acc[mf][2*nf2  ], al[mf], bh+0);
                #pragma unroll
                for (int mf = 0; mf < MF; mf++) mma16816(acc[mf][2*nf2+1], al[mf], bh+2);
            }
        }
    };

    stage(0);
    stage(1);
    for (int kc = 0; kc < NCH; kc++) {
        if (kc + 1 < NCH) { asm volatile("cp.async.wait_group 1;" ::: "memory"); }
        else              { asm volatile("cp.async.wait_group 0;" ::: "memory"); }
        __syncthreads();
        compute(kc);
        if (kc + STG - 1 < NCH) stage(kc + STG - 1);
    }

    // ---- epilogue ----
    const int lrow = lane >> 2, lcol = (lane & 3) * 2;
    #pragma unroll
    for (int mf = 0; mf < MF; mf++) {
        #pragma unroll
        for (int nf = 0; nf < NF; nf++) {
            const int oc = wn*NT + nf*8 + lcol;
            float bx = 0.f, by = 0.f;
            if (bias != nullptr) { bx = __ldg(bias + oc); by = __ldg(bias + oc + 1); }
            #pragma unroll
            for (int rp = 0; rp < 2; rp++) {
                const int m = wm*MT + mf*16 + lrow + rp*8;
                const int y = yb + (m >> 5), x = xb + (m & 31);
                float c0 = acc[mf][nf][rp*2] + bx;
                float c1 = acc[mf][nf][rp*2+1] + by;
                if (RELU) { c0 = fmaxf(c0, 0.f); c1 = fmaxf(c1, 0.f); }
                const size_t pix = (size_t)b*HW + (size_t)y*Ww + x;
                if (OUTK == 0) {
                    *(float2*)(outf + pix*OUT_CS + oc) = make_float2(c0, c1);
                } else {
                    __half h0 = __float2half_rn(c0);
                    __half l0 = __float2half_rn(c0 - __half2float(h0));
                    __half h1 = __float2half_rn(c1);
                    __half l1 = __float2half_rn(c1 - __half2float(h1));
                    __half* dst = outh + (pix*(N/32) + (oc >> 5))*64 + (oc & 31);
                    *(__half2*)dst        = __halves2half2(h0, h1);
                    *(__half2*)(dst + 32) = __halves2half2(l0, l1);
                }
            }
        }
    }
}

// ======= fused deformable sampling + 1x1 contraction (K=576 -> 64), fp32 NCHW out =======
// Gather now reads plain-fp16 hr (halved gather traffic); interpolation stays fp32.
__global__ void __launch_bounds__(256)
deform_mma(const __half* __restrict__ hrh, const float* __restrict__ offp,
           const __half* __restrict__ BT, float* __restrict__ outf)
{
    constexpr int N = 64, NCH = 18;
    constexpr int MF = 2, NF = 4;          // WM=4 (MT=32), WN=2 (NT=32)
    constexpr int ABUF = 128 * 128;
    constexpr int BBUF = N * 128;
    constexpr int BV = N / 32;

    extern __shared__ __align__(16) char dsm[];
    const uint32_t smb = (smem_u32(dsm) + 127u) & ~127u;
    const uint32_t Ab0 = smb, Ab1 = smb + ABUF;
    const uint32_t Bb0 = smb + 2*ABUF, Bb1 = smb + 2*ABUF + BBUF;

    const int t = threadIdx.x;
    const int w = t >> 5, lane = t & 31;
    const int wm = w % 4, wn = w / 4;
    const int xb = blockIdx.x * 32, yb = blockIdx.y * 4, b = blockIdx.z;

    float acc[MF][NF][4];
    #pragma unroll
    for (int i = 0; i < MF; i++)
        #pragma unroll
        for (int j = 0; j < NF; j++)
            #pragma unroll
            for (int r = 0; r < 4; r++) acc[i][j][r] = 0.f;

    const int px = t >> 1, half = t & 1;
    const int prow = px >> 5, pcol = px & 31;

    float4 avf[4];
    uint4  bv[BV];
    const __half *cp00 = nullptr, *cp01 = nullptr, *cp10 = nullptr, *cp11 = nullptr;
    float cw00 = 0.f, cw01 = 0.f, cw10 = 0.f, cw11 = 0.f;

    auto load_a = [&](int kc) {
        const int tap = kc >> 1;
        if ((kc & 1) == 0) {
            const int y = yb + prow, x = xb + pcol;
            const size_t pix = (size_t)b*HW + (size_t)y*Ww + x;
            const float dy = offp[pix*32 + 2*tap];
            const float dx = offp[pix*32 + 2*tap + 1];
            const float py  = (float)(y + tap/3 - 1) + dy;
            const float pxx = (float)(x + tap%3 - 1) + dx;
            const float y0f = floorf(py), x0f = floorf(pxx);
            const float wy = py - y0f, wx = pxx - x0f;
            const int yi = (int)y0f, xi = (int)x0f;
            const bool vy0 = (yi   >= 0) && (yi   <= Hh-1);
            const bool vy1 = (yi+1 >= 0) && (yi+1 <= Hh-1);
            const bool vx0 = (xi   >= 0) && (xi   <= Ww-1);
            const bool vx1 = (xi+1 >= 0) && (xi+1 <= Ww-1);
            const int yc0 = min(max(yi,   0), Hh-1);
            const int yc1 = min(max(yi+1, 0), Hh-1);
            const int xc0 = min(max(xi,   0), Ww-1);
            const int xc1 = min(max(xi+1, 0), Ww-1);
            cw00 = (1.f-wy)*(1.f-wx) * ((vy0 && vx0) ? 1.f : 0.f);
            cw01 = (1.f-wy)*wx       * ((vy0 && vx1) ? 1.f : 0.f);
            cw10 = wy*(1.f-wx)       * ((vy1 && vx0) ? 1.f : 0.f);
            cw11 = wy*wx             * ((vy1 && vx1) ? 1.f : 0.f);
            const __half* base = hrh + (size_t)b*HW*64;
            cp00 = base + ((size_t)yc0*Ww + xc0)*64;
            cp01 = base + ((size_t)yc0*Ww + xc1)*64;
            cp10 = base + ((size_t)yc1*Ww + xc0)*64;
            cp11 = base + ((size_t)yc1*Ww + xc1)*64;
        }
        const int cb = ((kc & 1) << 5) + half * 16;
        float2 f00[8], f01[8], f10[8], f11[8];
        gath16(cp00 + cb, f00);
        gath16(cp01 + cb, f01);
        gath16(cp10 + cb, f10);
        gath16(cp11 + cb, f11);
        #pragma unroll
        for (int i = 0; i < 8; i++) {
            const float vx = cw00*f00[i].x + cw01*f01[i].x + cw10*f10[i].x + cw11*f11[i].x;
            const float vy = cw00*f00[i].y + cw01*f01[i].y + cw10*f10[i].y + cw11*f11[i].y;
            if (i & 1) { avf[i>>1].z = vx; avf[i>>1].w = vy; }
            else       { avf[i>>1].x = vx; avf[i>>1].y = vy; }
        }
    };
    auto load_b = [&](int kc) {
        const uint4* src = (const uint4*)(BT + (size_t)kc*N*64);
        #pragma unroll
        for (int i = 0; i < BV; i++) bv[i] = src[t + i*256];
    };
    auto sts_ab = [&](uint32_t Ab, uint32_t Bb) {
        const uint32_t rowb = Ab + px*128;
        const uint32_t sw = px & 7;
        #pragma unroll
        for (int i = 0; i < 2; i++) {
            uint4 hi, lo;
            split8(avf[2*i], avf[2*i+1], hi, lo);
            const int ch = half*2 + i;
            st128(rowb + (uint32_t)((ch ^ sw) << 4), hi);
            st128(rowb + (uint32_t)(((ch+4) ^ sw) << 4), lo);
        }
        #pragma unroll
        for (int i = 0; i < BV; i++) st128(Bb + (t + i*256)*16, bv[i]);
    };
    auto compute = [&](uint32_t Ab, uint32_t Bb) {
        #pragma unroll
        for (int ks = 0; ks < 2; ks++) {
            uint32_t ah[MF][4], al[MF][4];
            #pragma unroll
            for (int mf = 0; mf < MF; mf++) {
                const int row = wm*32 + mf*16 + (lane & 15);
                const int chh = ks*2 + (lane >> 4);
                const uint32_t rb = Ab + row*128;
                ldm4(ah[mf], rb + (uint32_t)((chh ^ (row&7)) << 4));
                ldm4(al[mf], rb + (uint32_t)(((chh+4) ^ (row&7)) << 4));
            }
            #pragma unroll
            for (int nf2 = 0; nf2 < NF/2; nf2++) {
                uint32_t bh[4], bl[4];
                const int oc  = wn*32 + nf2*16 + (lane & 7) + ((lane >> 4) << 3);
                const int chb = ks*2 + ((lane >> 3) & 1);
                const uint32_t rb = Bb + oc*128;
                ldm4(bh, rb + (uint32_t)((chb ^ (oc&7)) << 4));
                ldm4(bl, rb + (uint32_t)(((chb+4) ^ (oc&7)) << 4));
                #pragma unroll
                for (int mf = 0; mf < MF; mf++) mma16816(acc[mf][2*nf2  ], ah[mf], bh+0);
                #pragma unroll
                for (int mf = 0; mf < MF; mf++) mma16816(acc[mf][2*nf2+1], ah[mf], bh+2);
                #pragma unroll
                for (int mf = 0; mf < MF; mf++) mma16816(acc[mf][2*nf2  ], ah[mf], bl+0);
                #pragma unroll
                for (int mf = 0; mf < MF; mf++) mma16816(acc[mf][2*nf2+1], ah[mf], bl+2);
                #pragma unroll
                for (int mf = 0; mf < MF; mf++) mma16816(acc[mf][2*nf2  ], al[mf], bh+0);
                #pragma unroll
                for (int mf = 0; mf < MF; mf++) mma16816(acc[mf][2*nf2+1], al[mf], bh+2);
            }
        }
    };

    load_a(0); load_b(0);
    sts_ab(Ab0, Bb0);
    __syncthreads();

    for (int kc = 0; kc < NCH; kc++) {
        if (kc + 1 < NCH) { load_a(kc+1); load_b(kc+1); }
        compute((kc & 1) ? Ab1 : Ab0, (kc & 1) ? Bb1 : Bb0);
        if (kc + 1 < NCH) {
            sts_ab(((kc+1) & 1) ? Ab1 : Ab0, ((kc+1) & 1) ? Bb1 : Bb0);
            __syncthreads();
        }
    }

    const int lrow = lane >> 2, lcol = (lane & 3) * 2;
    #pragma unroll
    for (int mf = 0; mf < MF; mf++) {
        #pragma unroll
        for (int nf = 0; nf < NF; nf++) {
            const int oc = wn*32 + nf*8 + lcol;
            #pragma unroll
            for (int rp = 0; rp < 2; rp++) {
                const int m = wm*32 + mf*16 + lrow + rp*8;
                const int y = yb + (m >> 5), x = xb + (m & 31);
                const size_t p = (size_t)y*Ww + x;
                outf[((size_t)b*N + oc  )*HW + p] = acc[mf][nf][rp*2];
                outf[((size_t)b*N + oc+1)*HW + p] = acc[mf][nf][rp*2+1];
            }
        }
    }
}

// ---------------- NCHW fp32 -> split fp16 NHWC chunks (+ optional plain fp16 NHWC) ----------------
__global__ void to_nhwc_split(const float* __restrict__ src, __half* __restrict__ dsts,
                              __half* __restrict__ dsth, int C)
{
    __shared__ float tl[32][33];
    const int p0 = blockIdx.x*32, c0 = blockIdx.y*32, b = blockIdx.z;
    const int lx = threadIdx.x & 31, ly = threadIdx.x >> 5;
    #pragma unroll
    for (int i = 0; i < 32; i += 8)
        tl[ly+i][lx] = src[((size_t)b*C + c0 + ly + i)*HW + p0 + lx];
    __syncthreads();
    const int CPT = C / 32;
    #pragma unroll
    for (int i = 0; i < 32; i += 8) {
        const int pix = p0 + ly + i, c = c0 + lx;
        const float v = tl[lx][ly+i];
        __half h = __float2half_rn(v);
        __half l = __float2half_rn(v - __half2float(h));
        __half* d = dsts + (((size_t)b*HW + pix)*CPT + (c >> 5))*64 + (c & 31);
        d[0]  = h;
        d[32] = l;
        if (dsth != nullptr) dsth[((size_t)b*HW + pix)*C + c] = h;
    }
}

// ---------------- weight reformat: split fp16 hi/lo + pre-swizzle smem image ----------------
__global__ void reformat_w_split(const float* __restrict__ w, __half* __restrict__ BT,
                                 int COUT, int NPAD, int CIN, int TOT)
{
    int i = blockIdx.x*blockDim.x + threadIdx.x;
    if (i >= TOT) return;
    int j  = i & 31;
    int oc = (i >> 5) % NPAD;
    int kc = i / (32 * NPAD);
    int kidx = kc*32 + j;
    int tap = kidx / CIN, cin = kidx % CIN;
    float v = (oc < COUT) ? w[((size_t)oc*CIN + cin)*9 + tap] : 0.f;
    __half h = __float2half_rn(v);
    __half l = __float2half_rn(v - __half2float(h));
    int sw = oc & 7;
    size_t rowb = ((size_t)kc*NPAD + oc) * 64;
    int ch = j >> 3, pos = j & 7;
    BT[rowb + (size_t)(((ch    ) ^ sw) << 3) + pos] = h;
    BT[rowb + (size_t)(((ch + 4) ^ sw) << 3) + pos] = l;
}

// ---------------- launch ----------------
extern "C" void kernel_launch(void* const* d_in, const int* in_sizes, int n_in,
                              void* d_out, int out_size)
{
    (void)in_sizes; (void)n_in; (void)out_size;
    const float* lr = (const float*)d_in[0];
    const float* hr = (const float*)d_in[1];
    const float* w1 = (const float*)d_in[2];
    const float* b1 = (const float*)d_in[3];
    const float* w2 = (const float*)d_in[4];
    const float* b2 = (const float*)d_in[5];
    const float* wo = (const float*)d_in[6];
    const float* wd = (const float*)d_in[7];
    float* out = (float*)d_out;

    __half *plrs, *phrs, *ph1s, *ph2s, *phrh, *pBT1, *pBT2, *pBTo, *pBTd;
    float *poff;
    cudaGetSymbolAddress((void**)&plrs, g_lrs);
    cudaGetSymbolAddress((void**)&phrs, g_hrs);
    cudaGetSymbolAddress((void**)&ph1s, g_h1s);
    cudaGetSymbolAddress((void**)&ph2s, g_h2s);
    cudaGetSymbolAddress((void**)&phrh, g_hrh);
    cudaGetSymbolAddress((void**)&poff, g_off);
    cudaGetSymbolAddress((void**)&pBT1, g_BT1);
    cudaGetSymbolAddress((void**)&pBT2, g_BT2);
    cudaGetSymbolAddress((void**)&pBTo, g_BTo);
    cudaGetSymbolAddress((void**)&pBTd, g_BTd);

    const int SZ128 = 3*(16384 + 128*128);   // 98304
    const int SZ32  = 3*(16384 + 32*128);    // 61440
    const int SZD   = 2*16384 + 2*64*128;    // 49152
    cudaFuncSetAttribute(mma_conv_cp<128,2,1,true ,36,4>,
                         cudaFuncAttributeMaxDynamicSharedMemorySize, SZ128);
    cudaFuncSetAttribute(mma_conv_cp<32 ,1,0,false,36,4>,
                         cudaFuncAttributeMaxDynamicSharedMemorySize, SZ32);
    cudaFuncSetAttribute(deform_mma,
                         cudaFuncAttributeMaxDynamicSharedMemorySize, SZD);

    // launch order: conv1 at index 3 (ncu profiles launch index 3)
    reformat_w_split<<<(36*128*32+255)/256, 256>>>(w1, pBT1, 128, 128, 128, 36*128*32); // 0
    to_nhwc_split<<<dim3(800,2,Bn), 256>>>(lr, plrs, nullptr, 64);                      // 1
    to_nhwc_split<<<dim3(800,2,Bn), 256>>>(hr, phrs, phrh,    64);                      // 2

    // conv1: concat(lr|hr)(128) -> 128, relu, split-fp16 out   [launch 3: PROFILED]
    mma_conv_cp<128,2,1,true ,36,4><<<dim3(5,40,Bn), 128, SZ128>>>(
        plrs, phrs, pBT1, b1, nullptr, ph1s, 2, 2, 2, 0);

    reformat_w_split<<<(36*128*32+255)/256, 256>>>(w2, pBT2, 128, 128, 128, 36*128*32); // 4
    reformat_w_split<<<(36*32*32 +255)/256, 256>>>(wo, pBTo, 18,  32,  128, 36*32*32);  // 5
    reformat_w_split<<<(18*64*32 +255)/256, 256>>>(wd, pBTd, 64,  64,  64,  18*64*32);  // 6

    // conv2: 128 -> 128, relu, split-fp16 out
    mma_conv_cp<128,2,1,true ,36,4><<<dim3(5,40,Bn), 128, SZ128>>>(
        ph1s, ph1s, pBT2, b2, nullptr, ph2s, 4, 4, 4, 0);
    // offset conv: 128 -> 18 (pad 32), fp32 NHWC out
    mma_conv_cp<32 ,1,0,false,36,4><<<dim3(5,40,Bn), 128, SZ32 >>>(
        ph2s, ph2s, pBTo, nullptr, poff, nullptr, 4, 4, 4, 32);
    // fused deformable sampling + contraction: K=576 -> 64, fp32 NCHW out
    deform_mma<<<dim3(5,40,Bn), 256, SZD>>>(phrh, poff, pBTd, out);
}